// round 1
// baseline (speedup 1.0000x reference)
#include <cuda_runtime.h>
#include <cuda_bf16.h>
#include <math.h>

// Problem constants
constexpr int Bsz = 2;
constexpr int Tseq = 1024;
constexpr int Cdim = 1024;
constexpr int Hn   = 16;
constexpr int Dh   = 64;
constexpr int Ln   = 4;
constexpr int Vn   = 32000;
constexpr int NFF  = 4096;
constexpr int BT   = Bsz * Tseq;       // 2048 token rows

// Scratch (device globals; no allocation allowed)
__device__ float g_x  [BT * Cdim];          // residual stream
__device__ float g_nx [BT * Cdim];          // LN output
__device__ float g_qk [BT * 2 * Cdim];      // packed q,k projections
__device__ float g_y  [BT * Cdim];          // attention branch output
__device__ float g_pm [BT * Cdim];          // prefix-mean of nx (per batch, per channel)
__device__ float g_ff [BT * NFF];           // MLP hidden
__device__ float g_cs [8 * Bsz * Cdim];     // chunk sums for prefix scan

// ---------------------------------------------------------------------------
// Embedding: x[b,t,c] = wte[ids[b,t],c] + wpe[t,c]
// ---------------------------------------------------------------------------
__global__ void __launch_bounds__(256)
embed_kernel(const int* __restrict__ ids, const float* __restrict__ wte,
             const float* __restrict__ wpe)
{
    int i = blockIdx.x * 256 + threadIdx.x;       // over BT*C/4
    int base = i * 4;
    int bt = base >> 10;                          // / C
    int c  = base & 1023;
    int t  = bt & 1023;                           // bt % T
    int id = ids[bt];
    float4 a = *(const float4*)(wte + (size_t)id * Cdim + c);
    float4 p = *(const float4*)(wpe + (size_t)t  * Cdim + c);
    float4 o;
    o.x = a.x + p.x; o.y = a.y + p.y; o.z = a.z + p.z; o.w = a.w + p.w;
    *(float4*)(g_x + (size_t)bt * Cdim + c) = o;
}

// ---------------------------------------------------------------------------
// LayerNorm (bias=False, eps=1e-5): one block per row, 256 threads, C=1024
// ---------------------------------------------------------------------------
__global__ void __launch_bounds__(256)
ln_kernel(const float* __restrict__ x, const float* __restrict__ w,
          float* __restrict__ out)
{
    __shared__ float red[8];
    __shared__ float stat[2];
    int row = blockIdx.x;
    int tid = threadIdx.x;
    const float* xr = x + (size_t)row * Cdim;
    float4 v = *(const float4*)(xr + tid * 4);

    float s = v.x + v.y + v.z + v.w;
    #pragma unroll
    for (int o = 16; o; o >>= 1) s += __shfl_xor_sync(0xffffffffu, s, o);
    if ((tid & 31) == 0) red[tid >> 5] = s;
    __syncthreads();
    if (tid < 8) {
        s = red[tid];
        #pragma unroll
        for (int o = 4; o; o >>= 1) s += __shfl_xor_sync(0xffu, s, o);
        if (tid == 0) stat[0] = s * (1.0f / Cdim);
    }
    __syncthreads();
    float mu = stat[0];
    float dx = v.x - mu, dy = v.y - mu, dz = v.z - mu, dw = v.w - mu;
    s = dx * dx + dy * dy + dz * dz + dw * dw;
    #pragma unroll
    for (int o = 16; o; o >>= 1) s += __shfl_xor_sync(0xffffffffu, s, o);
    if ((tid & 31) == 0) red[tid >> 5] = s;
    __syncthreads();
    if (tid < 8) {
        s = red[tid];
        #pragma unroll
        for (int o = 4; o; o >>= 1) s += __shfl_xor_sync(0xffu, s, o);
        if (tid == 0) stat[1] = rsqrtf(s * (1.0f / Cdim) + 1e-5f);
    }
    __syncthreads();
    float rstd = stat[1];
    float4 g = *(const float4*)(w + tid * 4);
    float4 o;
    o.x = dx * rstd * g.x; o.y = dy * rstd * g.y;
    o.z = dz * rstd * g.z; o.w = dw * rstd * g.w;
    *(float4*)(out + (size_t)row * Cdim + tid * 4) = o;
}

// ---------------------------------------------------------------------------
// Prefix-mean of nx over t (per batch, per channel): pm[b,t,c] = mean_{s<=t} nx[b,s,c]
// Two-phase scan: 8 chunks of 128 along T.
// ---------------------------------------------------------------------------
__global__ void __launch_bounds__(256)
pm_phase1(const float* __restrict__ nx)
{
    int g = blockIdx.x * 256 + threadIdx.x;       // 8 * B * C = 16384
    int chunk = g >> 11;                          // / (B*C)
    int bc = g & 2047;
    int b = bc >> 10, c = bc & 1023;
    const float* p = nx + (size_t)(b * Tseq + chunk * 128) * Cdim + c;
    float s = 0.f;
    #pragma unroll 8
    for (int i = 0; i < 128; i++) s += p[(size_t)i * Cdim];
    g_cs[g] = s;
}

__global__ void __launch_bounds__(256)
pm_phase2(const float* __restrict__ nx, float* __restrict__ pm)
{
    int g = blockIdx.x * 256 + threadIdx.x;
    int chunk = g >> 11;
    int bc = g & 2047;
    int b = bc >> 10, c = bc & 1023;
    float s = 0.f;
    for (int j = 0; j < chunk; j++) s += g_cs[j * 2048 + bc];
    const float* p = nx + (size_t)(b * Tseq + chunk * 128) * Cdim + c;
    float* o = pm + (size_t)(b * Tseq + chunk * 128) * Cdim + c;
    #pragma unroll 4
    for (int i = 0; i < 128; i++) {
        s += p[(size_t)i * Cdim];
        o[(size_t)i * Cdim] = __fdividef(s, (float)(chunk * 128 + i + 1));
    }
}

// ---------------------------------------------------------------------------
// Generic NT GEMM: C[M,N] = A[M,K] (row-major) * B[N,K]^T (row-major)
// 128x128 block tile, BK=16, 8x8 per-thread microtile, 256 threads.
// Epilogue modes: 0 = store, 1 = exact GELU, 2 = residual combine:
//   out = rx + c1[layer]*ry + c2[layer]*acc
// M, N assumed multiples of 128; K multiple of 16.
// ---------------------------------------------------------------------------
#define GMODE_NONE 0
#define GMODE_GELU 1
#define GMODE_RES  2

__global__ void __launch_bounds__(256, 2)
gemm_nt(const float* __restrict__ A, const float* __restrict__ B,
        float* __restrict__ C, int M, int N, int K, int mode,
        const float* __restrict__ rx, const float* __restrict__ ry,
        const float* __restrict__ c1, const float* __restrict__ c2, int layer)
{
    __shared__ float sA[16][128];
    __shared__ float sB[16][128];
    const int bm = blockIdx.y * 128;
    const int bn = blockIdx.x * 128;
    const int tid = threadIdx.x;
    const int tx = tid & 15;       // N direction
    const int ty = tid >> 4;       // M direction
    const int lr = tid >> 2;       // load row 0..63
    const int lk = (tid & 3) * 4;  // load k offset 0,4,8,12

    const float* Ab = A + (size_t)(bm + lr) * K + lk;
    const float* Bb = B + (size_t)(bn + lr) * K + lk;
    const size_t arow64 = (size_t)64 * K;

    float acc[8][8];
    #pragma unroll
    for (int i = 0; i < 8; i++)
        #pragma unroll
        for (int j = 0; j < 8; j++) acc[i][j] = 0.f;

    for (int k0 = 0; k0 < K; k0 += 16) {
        float4 a0 = *(const float4*)(Ab + k0);
        float4 a1 = *(const float4*)(Ab + k0 + arow64);
        float4 b0 = *(const float4*)(Bb + k0);
        float4 b1 = *(const float4*)(Bb + k0 + arow64);
        __syncthreads();
        sA[lk + 0][lr] = a0.x; sA[lk + 1][lr] = a0.y;
        sA[lk + 2][lr] = a0.z; sA[lk + 3][lr] = a0.w;
        sA[lk + 0][lr + 64] = a1.x; sA[lk + 1][lr + 64] = a1.y;
        sA[lk + 2][lr + 64] = a1.z; sA[lk + 3][lr + 64] = a1.w;
        sB[lk + 0][lr] = b0.x; sB[lk + 1][lr] = b0.y;
        sB[lk + 2][lr] = b0.z; sB[lk + 3][lr] = b0.w;
        sB[lk + 0][lr + 64] = b1.x; sB[lk + 1][lr + 64] = b1.y;
        sB[lk + 2][lr + 64] = b1.z; sB[lk + 3][lr + 64] = b1.w;
        __syncthreads();
        #pragma unroll
        for (int k = 0; k < 16; k++) {
            float4 ra0 = *(const float4*)&sA[k][ty * 8];
            float4 ra1 = *(const float4*)&sA[k][ty * 8 + 4];
            float4 rb0 = *(const float4*)&sB[k][tx * 8];
            float4 rb1 = *(const float4*)&sB[k][tx * 8 + 4];
            float a[8] = {ra0.x, ra0.y, ra0.z, ra0.w, ra1.x, ra1.y, ra1.z, ra1.w};
            float b[8] = {rb0.x, rb0.y, rb0.z, rb0.w, rb1.x, rb1.y, rb1.z, rb1.w};
            #pragma unroll
            for (int i = 0; i < 8; i++)
                #pragma unroll
                for (int j = 0; j < 8; j++)
                    acc[i][j] = fmaf(a[i], b[j], acc[i][j]);
        }
    }

    float f1 = 0.f, f2 = 0.f;
    if (mode == GMODE_RES) { f1 = c1[layer]; f2 = c2[layer]; }

    #pragma unroll
    for (int i = 0; i < 8; i++) {
        int row = bm + ty * 8 + i;
        size_t ro = (size_t)row * N + bn + tx * 8;
        #pragma unroll
        for (int jj = 0; jj < 2; jj++) {
            float4 v;
            v.x = acc[i][jj * 4 + 0]; v.y = acc[i][jj * 4 + 1];
            v.z = acc[i][jj * 4 + 2]; v.w = acc[i][jj * 4 + 3];
            if (mode == GMODE_GELU) {
                v.x = 0.5f * v.x * (1.f + erff(v.x * 0.70710678118654752f));
                v.y = 0.5f * v.y * (1.f + erff(v.y * 0.70710678118654752f));
                v.z = 0.5f * v.z * (1.f + erff(v.z * 0.70710678118654752f));
                v.w = 0.5f * v.w * (1.f + erff(v.w * 0.70710678118654752f));
            } else if (mode == GMODE_RES) {
                float4 x0 = *(const float4*)(rx + ro + jj * 4);
                float4 y0 = *(const float4*)(ry + ro + jj * 4);
                v.x = x0.x + f1 * y0.x + f2 * v.x;
                v.y = x0.y + f1 * y0.y + f2 * v.y;
                v.z = x0.z + f1 * y0.z + f2 * v.z;
                v.w = x0.w + f1 * y0.w + f2 * v.w;
            }
            *(float4*)(C + ro + jj * 4) = v;
        }
    }
}

// ---------------------------------------------------------------------------
// Fused causal attention + shaped-attention epilogue.
//   y = beta * softmax(QK^T * scale, causal) @ V + alpha * V_row - gamma * pm
// Q,K from g_qk (packed [BT, 2C]); V = nx (head-sliced). D=64.
// Block: 256 threads, one 64-row q tile for one (b,h). Online softmax in regs.
// smem: Q tile + K/P tile (aliased) + V tile = 3 * 64*68*4 = 52,224 B < 48KB?
// 64*68*4 = 17,408 * 3 = 52,224 > 49,152 -> use 64x64 for Q (reads are
// broadcast-friendly), padded 64x68 for K/P and V (strided column mapping
// keeps those reads ~conflict-free).  16384 + 17408*2 = 51,200 ... still over.
// -> Q stored 64x64 (16KB), K/P 64x68, V 64x64 with strided col mapping for V
//    reads being broadcast across ty is false... V reads are per-k row,
//    col = tx+16j -> bank = (64k + tx+16j)%32 = (tx+16j)%32 -> conflict-free.
//    Total = 16384 + 17408 + 16384 = 50,176 > 49,152. Trim K/P pad to 66:
//    64*66*4 = 16,896 -> total 49,664 > 49,152. Pad 65 (scalar access only):
//    64*65*4 = 16,640 -> total 49,408 > 49,152. So drop Q pad entirely and
//    use K/P pad 64: K reads col-mapped give bank=(4r+d)... keep it simple:
//    Q 64x64, V 64x64, KP 64x64 = 48KB exactly; K reads in S-compute use
//    strided col mapping c=tx+16j -> bank=(64*(tx+16j)+d)%32 = d%32 -> all
//    lanes same bank BUT different addresses only in row -> 16-way conflict.
//    Instead store K TRANSPOSED (sKT[d][c]): S reads sKT[d][tx+16j] ->
//    bank=(64d + tx+16j)%32 = (tx+16j)%32 -> conflict-free. P (written after
//    S) is stored into the same buffer in [r][c] layout (row-major), and PV
//    reads sP[r][k] (2 addresses/warp, broadcast) - fine.
// ---------------------------------------------------------------------------
__global__ void __launch_bounds__(256)
attn_kernel(const float* __restrict__ qkbuf, const float* __restrict__ nx,
            const float* __restrict__ pm, float* __restrict__ y,
            const float* __restrict__ al, const float* __restrict__ be,
            const float* __restrict__ ga, int layer)
{
    __shared__ float sQ[64][64];    // [r][d]
    __shared__ float sKP[64][64];   // K as [d][c] (transposed); later P as [r][c]
    __shared__ float sV[64][64];    // [k][c]
    const int qt = blockIdx.x;           // q tile 0..15
    const int bh = blockIdx.y;           // 0..31
    const int b = bh >> 4;
    const int h = bh & 15;
    const int tid = threadIdx.x;
    const int tx = tid & 15;
    const int ty = tid >> 4;
    const int q0 = qt * 64;
    const float scale = 0.125f;          // 64^-0.5

    // Load Q tile (scaled)
    for (int i = tid; i < 64 * 16; i += 256) {
        int r = i >> 4, c4 = (i & 15) * 4;
        float4 v = *(const float4*)(qkbuf + (size_t)(b * Tseq + q0 + r) * (2 * Cdim)
                                    + h * 64 + c4);
        sQ[r][c4 + 0] = v.x * scale; sQ[r][c4 + 1] = v.y * scale;
        sQ[r][c4 + 2] = v.z * scale; sQ[r][c4 + 3] = v.w * scale;
    }

    float o[4][4];
    #pragma unroll
    for (int i = 0; i < 4; i++)
        #pragma unroll
        for (int j = 0; j < 4; j++) o[i][j] = 0.f;
    float mrow[4], lrow[4];
    #pragma unroll
    for (int i = 0; i < 4; i++) { mrow[i] = -INFINITY; lrow[i] = 0.f; }

    for (int jt = 0; jt <= qt; jt++) {
        int k0 = jt * 64;
        __syncthreads();   // protect sKP/sV reuse from previous iteration (and Q at jt=0)
        for (int i = tid; i < 64 * 16; i += 256) {
            int r = i >> 4, c4 = (i & 15) * 4;
            float4 kv = *(const float4*)(qkbuf + (size_t)(b * Tseq + k0 + r) * (2 * Cdim)
                                         + Cdim + h * 64 + c4);
            // transposed store: sKP[d][c=r]
            sKP[c4 + 0][r] = kv.x; sKP[c4 + 1][r] = kv.y;
            sKP[c4 + 2][r] = kv.z; sKP[c4 + 3][r] = kv.w;
            float4 vv = *(const float4*)(nx + (size_t)(b * Tseq + k0 + r) * Cdim
                                         + h * 64 + c4);
            sV[r][c4 + 0] = vv.x; sV[r][c4 + 1] = vv.y;
            sV[r][c4 + 2] = vv.z; sV[r][c4 + 3] = vv.w;
        }
        __syncthreads();

        // S fragment: rows r = ty*4+i, cols c = tx + 16*j
        float s[4][4];
        #pragma unroll
        for (int i = 0; i < 4; i++)
            #pragma unroll
            for (int j = 0; j < 4; j++) s[i][j] = 0.f;
        #pragma unroll 8
        for (int d = 0; d < 64; d++) {
            float qv[4], kv[4];
            #pragma unroll
            for (int i = 0; i < 4; i++) qv[i] = sQ[ty * 4 + i][d];
            #pragma unroll
            for (int j = 0; j < 4; j++) kv[j] = sKP[d][tx + 16 * j];
            #pragma unroll
            for (int i = 0; i < 4; i++)
                #pragma unroll
                for (int j = 0; j < 4; j++)
                    s[i][j] = fmaf(qv[i], kv[j], s[i][j]);
        }
        if (jt == qt) {
            #pragma unroll
            for (int i = 0; i < 4; i++)
                #pragma unroll
                for (int j = 0; j < 4; j++)
                    if (tx + 16 * j > ty * 4 + i) s[i][j] = -INFINITY;
        }

        // Online softmax across the 16 lanes of each row group (width-16 shuffles)
        float corr[4];
        #pragma unroll
        for (int i = 0; i < 4; i++) {
            float mt = fmaxf(fmaxf(s[i][0], s[i][1]), fmaxf(s[i][2], s[i][3]));
            #pragma unroll
            for (int off = 8; off; off >>= 1)
                mt = fmaxf(mt, __shfl_xor_sync(0xffffffffu, mt, off, 16));
            float mnew = fmaxf(mrow[i], mt);
            corr[i] = __expf(mrow[i] - mnew);
            mrow[i] = mnew;
            float sum = 0.f;
            #pragma unroll
            for (int j = 0; j < 4; j++) {
                s[i][j] = __expf(s[i][j] - mnew);
                sum += s[i][j];
            }
            #pragma unroll
            for (int off = 8; off; off >>= 1)
                sum += __shfl_xor_sync(0xffffffffu, sum, off, 16);
            lrow[i] = lrow[i] * corr[i] + sum;
        }

        __syncthreads();   // everyone done reading K from sKP
        #pragma unroll
        for (int i = 0; i < 4; i++)
            #pragma unroll
            for (int j = 0; j < 4; j++)
                sKP[ty * 4 + i][tx + 16 * j] = s[i][j];   // P, row-major
        __syncthreads();

        #pragma unroll
        for (int i = 0; i < 4; i++)
            #pragma unroll
            for (int j = 0; j < 4; j++) o[i][j] *= corr[i];
        #pragma unroll 8
        for (int k = 0; k < 64; k++) {
            float pv[4], vv[4];
            #pragma unroll
            for (int i = 0; i < 4; i++) pv[i] = sKP[ty * 4 + i][k];
            #pragma unroll
            for (int j = 0; j < 4; j++) vv[j] = sV[k][tx + 16 * j];
            #pragma unroll
            for (int i = 0; i < 4; i++)
                #pragma unroll
                for (int j = 0; j < 4; j++)
                    o[i][j] = fmaf(pv[i], vv[j], o[i][j]);
        }
    }

    float alpha = al[layer], beta = be[layer], gamma = ga[layer];
    #pragma unroll
    for (int i = 0; i < 4; i++) {
        int r = q0 + ty * 4 + i;
        size_t base = (size_t)(b * Tseq + r) * Cdim + h * 64;
        float inv = __fdividef(1.f, lrow[i]);
        #pragma unroll
        for (int j = 0; j < 4; j++) {
            int c = tx + 16 * j;
            y[base + c] = beta * o[i][j] * inv + alpha * nx[base + c]
                          - gamma * pm[base + c];
        }
    }
}

// ---------------------------------------------------------------------------
// Host orchestration
// ---------------------------------------------------------------------------
extern "C" void kernel_launch(void* const* d_in, const int* in_sizes, int n_in,
                              void* d_out, int out_size)
{
    (void)in_sizes; (void)n_in; (void)out_size;
    const int*   ids   = (const int*)  d_in[0];
    const float* wte   = (const float*)d_in[1];
    const float* wpe   = (const float*)d_in[2];
    const float* Wattn = (const float*)d_in[3];
    const float* Wfc   = (const float*)d_in[4];
    const float* Wproj = (const float*)d_in[5];
    const float* ln_w  = (const float*)d_in[6];
    const float* alpha = (const float*)d_in[7];
    const float* beta  = (const float*)d_in[8];
    const float* gamma = (const float*)d_in[9];
    const float* bSA   = (const float*)d_in[10];
    const float* bFF   = (const float*)d_in[11];
    const float* lnf_w = (const float*)d_in[12];
    float* out = (float*)d_out;

    float *x, *nx, *qk, *y, *pm, *ff;
    cudaGetSymbolAddress((void**)&x,  g_x);
    cudaGetSymbolAddress((void**)&nx, g_nx);
    cudaGetSymbolAddress((void**)&qk, g_qk);
    cudaGetSymbolAddress((void**)&y,  g_y);
    cudaGetSymbolAddress((void**)&pm, g_pm);
    cudaGetSymbolAddress((void**)&ff, g_ff);

    embed_kernel<<<BT * Cdim / 4 / 256, 256>>>(ids, wte, wpe);

    for (int i = 0; i < Ln; i++) {
        ln_kernel<<<BT, 256>>>(x, ln_w + (size_t)i * Cdim, nx);
        pm_phase1<<<64, 256>>>(nx);
        pm_phase2<<<64, 256>>>(nx, pm);
        // qk = nx @ Wattn[i]^T : [BT, 2C]
        gemm_nt<<<dim3(2 * Cdim / 128, BT / 128), 256>>>(
            nx, Wattn + (size_t)i * 2 * Cdim * Cdim, qk,
            BT, 2 * Cdim, Cdim, GMODE_NONE, nullptr, nullptr, nullptr, nullptr, 0);
        // attention branch -> y
        attn_kernel<<<dim3(Tseq / 64, Bsz * Hn), 256>>>(
            qk, nx, pm, y, alpha, beta, gamma, i);
        // h = gelu(nx @ Wfc[i]^T) : [BT, NFF]
        gemm_nt<<<dim3(NFF / 128, BT / 128), 256>>>(
            nx, Wfc + (size_t)i * NFF * Cdim, ff,
            BT, NFF, Cdim, GMODE_GELU, nullptr, nullptr, nullptr, nullptr, 0);
        // x = x + bSA*y + bFF*(h @ Wproj[i]^T)
        gemm_nt<<<dim3(Cdim / 128, BT / 128), 256>>>(
            ff, Wproj + (size_t)i * Cdim * NFF, x,
            BT, Cdim, NFF, GMODE_RES, x, y, bSA, bFF, i);
    }

    ln_kernel<<<BT, 256>>>(x, lnf_w, nx);
    // logits = nx @ wte^T : [BT, V]
    gemm_nt<<<dim3(Vn / 128, BT / 128), 256>>>(
        nx, wte, out, BT, Vn, Cdim, GMODE_NONE,
        nullptr, nullptr, nullptr, nullptr, 0);
}

// round 5
// speedup vs baseline: 2.6251x; 2.6251x over previous
#include <cuda_runtime.h>
#include <cuda_bf16.h>
#include <math.h>
#include <stdint.h>

// Problem constants
constexpr int Bsz = 2;
constexpr int Tseq = 1024;
constexpr int Cdim = 1024;
constexpr int Hn   = 16;
constexpr int Ln   = 4;
constexpr int Vn   = 32000;
constexpr int NFF  = 4096;
constexpr int BT   = Bsz * Tseq;       // 2048 token rows

// Scratch (device globals; no allocation allowed)
__device__ float g_x  [BT * Cdim];          // residual stream
__device__ float g_nx [BT * Cdim];          // LN output
__device__ float g_qk [BT * 2 * Cdim];      // packed q,k projections
__device__ float g_y  [BT * Cdim];          // attention branch output
__device__ float g_pm [BT * Cdim];          // prefix-mean of nx
__device__ float g_ff [BT * NFF];           // MLP hidden
__device__ float g_cs [8 * Bsz * Cdim];     // chunk sums for prefix scan

// ---------------------------------------------------------------------------
// PTX helpers: tf32 convert (rna = unbiased), ldmatrix, mma
// ---------------------------------------------------------------------------
__device__ __forceinline__ float f2tf(float x) {
    uint32_t r;
    asm("cvt.rna.tf32.f32 %0, %1;" : "=r"(r) : "f"(x));
    return __uint_as_float(r);
}
__device__ __forceinline__ void ldsm4(uint32_t* r, const float* p) {
    uint32_t a = (uint32_t)__cvta_generic_to_shared(p);
    asm volatile("ldmatrix.sync.aligned.m8n8.x4.shared.b16 {%0,%1,%2,%3}, [%4];"
                 : "=r"(r[0]), "=r"(r[1]), "=r"(r[2]), "=r"(r[3]) : "r"(a));
}
__device__ __forceinline__ void mma8(float* c, const uint32_t* a, const uint32_t* b) {
    asm volatile(
        "mma.sync.aligned.m16n8k8.row.col.f32.tf32.tf32.f32 "
        "{%0,%1,%2,%3}, {%4,%5,%6,%7}, {%8,%9}, {%0,%1,%2,%3};"
        : "+f"(c[0]), "+f"(c[1]), "+f"(c[2]), "+f"(c[3])
        : "r"(a[0]), "r"(a[1]), "r"(a[2]), "r"(a[3]), "r"(b[0]), "r"(b[1]));
}

// ---------------------------------------------------------------------------
// Embedding
// ---------------------------------------------------------------------------
__global__ void __launch_bounds__(256)
embed_kernel(const int* __restrict__ ids, const float* __restrict__ wte,
             const float* __restrict__ wpe)
{
    int i = blockIdx.x * 256 + threadIdx.x;
    int base = i * 4;
    int bt = base >> 10;
    int c  = base & 1023;
    int t  = bt & 1023;
    int id = ids[bt];
    float4 a = *(const float4*)(wte + (size_t)id * Cdim + c);
    float4 p = *(const float4*)(wpe + (size_t)t  * Cdim + c);
    float4 o;
    o.x = a.x + p.x; o.y = a.y + p.y; o.z = a.z + p.z; o.w = a.w + p.w;
    *(float4*)(g_x + (size_t)bt * Cdim + c) = o;
}

// ---------------------------------------------------------------------------
// LayerNorm (bias=False, eps=1e-5)
// ---------------------------------------------------------------------------
__global__ void __launch_bounds__(256)
ln_kernel(const float* __restrict__ x, const float* __restrict__ w,
          float* __restrict__ out)
{
    __shared__ float red[8];
    __shared__ float stat[2];
    int row = blockIdx.x;
    int tid = threadIdx.x;
    const float* xr = x + (size_t)row * Cdim;
    float4 v = *(const float4*)(xr + tid * 4);

    float s = v.x + v.y + v.z + v.w;
    #pragma unroll
    for (int o = 16; o; o >>= 1) s += __shfl_xor_sync(0xffffffffu, s, o);
    if ((tid & 31) == 0) red[tid >> 5] = s;
    __syncthreads();
    if (tid < 8) {
        s = red[tid];
        #pragma unroll
        for (int o = 4; o; o >>= 1) s += __shfl_xor_sync(0xffu, s, o);
        if (tid == 0) stat[0] = s * (1.0f / Cdim);
    }
    __syncthreads();
    float mu = stat[0];
    float dx = v.x - mu, dy = v.y - mu, dz = v.z - mu, dw = v.w - mu;
    s = dx * dx + dy * dy + dz * dz + dw * dw;
    #pragma unroll
    for (int o = 16; o; o >>= 1) s += __shfl_xor_sync(0xffffffffu, s, o);
    if ((tid & 31) == 0) red[tid >> 5] = s;
    __syncthreads();
    if (tid < 8) {
        s = red[tid];
        #pragma unroll
        for (int o = 4; o; o >>= 1) s += __shfl_xor_sync(0xffu, s, o);
        if (tid == 0) stat[1] = rsqrtf(s * (1.0f / Cdim) + 1e-5f);
    }
    __syncthreads();
    float rstd = stat[1];
    float4 g = *(const float4*)(w + tid * 4);
    float4 o;
    o.x = dx * rstd * g.x; o.y = dy * rstd * g.y;
    o.z = dz * rstd * g.z; o.w = dw * rstd * g.w;
    *(float4*)(out + (size_t)row * Cdim + tid * 4) = o;
}

// ---------------------------------------------------------------------------
// Prefix-mean scan
// ---------------------------------------------------------------------------
__global__ void __launch_bounds__(256)
pm_phase1(const float* __restrict__ nx)
{
    int g = blockIdx.x * 256 + threadIdx.x;
    int chunk = g >> 11;
    int bc = g & 2047;
    int b = bc >> 10, c = bc & 1023;
    const float* p = nx + (size_t)(b * Tseq + chunk * 128) * Cdim + c;
    float s = 0.f;
    #pragma unroll 8
    for (int i = 0; i < 128; i++) s += p[(size_t)i * Cdim];
    g_cs[g] = s;
}

__global__ void __launch_bounds__(256)
pm_phase2(const float* __restrict__ nx, float* __restrict__ pm)
{
    int g = blockIdx.x * 256 + threadIdx.x;
    int chunk = g >> 11;
    int bc = g & 2047;
    int b = bc >> 10, c = bc & 1023;
    float s = 0.f;
    for (int j = 0; j < chunk; j++) s += g_cs[j * 2048 + bc];
    const float* p = nx + (size_t)(b * Tseq + chunk * 128) * Cdim + c;
    float* o = pm + (size_t)(b * Tseq + chunk * 128) * Cdim + c;
    #pragma unroll 4
    for (int i = 0; i < 128; i++) {
        s += p[(size_t)i * Cdim];
        o[(size_t)i * Cdim] = __fdividef(s, (float)(chunk * 128 + i + 1));
    }
}

// ---------------------------------------------------------------------------
// tf32 tensor-core NT GEMM: C[M,N] = A[M,K] * B[N,K]^T (both row-major fp32)
// 128x128 block tile, BK=32, 8 warps, warp tile 32x64 (2 m16 x 8 n8 mma tiles).
// Data converted to tf32 (rna) at smem store; mma.sync.m16n8k8.tf32 compute.
// Epilogues: 0=store, 1=exact GELU, 2=residual combine out = rx + c1*ry + c2*acc
// Requires M%128==0, N%128==0, K%32==0 (true for all call sites).
// ---------------------------------------------------------------------------
#define GMODE_NONE 0
#define GMODE_GELU 1
#define GMODE_RES  2

__global__ void __launch_bounds__(256, 2)
gemm_nt_tf32(const float* __restrict__ A, const float* __restrict__ B,
             float* __restrict__ C, int M, int N, int K, int mode,
             const float* __restrict__ rx, const float* __restrict__ ry,
             const float* __restrict__ c1v, const float* __restrict__ c2v,
             int layer)
{
    __shared__ float sA[128][36];   // [m][k], +4 pad keeps ldmatrix rows conflict-free
    __shared__ float sB[128][36];   // [n][k]

    const int tid  = threadIdx.x;
    const int bm   = blockIdx.y * 128;
    const int bn   = blockIdx.x * 128;
    const int lane = tid & 31;
    const int warp = tid >> 5;
    const int wm   = warp >> 1;     // 0..3 : m offset wm*32
    const int wn   = warp & 1;      // 0..1 : n offset wn*64

    // gmem staging map: each thread 4 float4 per matrix
    const int lrow = tid >> 3;          // 0..31
    const int lcol = (tid & 7) * 4;     // 0..28

    const float* Ag = A + (size_t)(bm + lrow) * K + lcol;
    const float* Bg = B + (size_t)(bn + lrow) * K + lcol;

    float4 ra[4], rb[4];
    #pragma unroll
    for (int i = 0; i < 4; i++) {
        ra[i] = *(const float4*)(Ag + (size_t)(32 * i) * K);
        rb[i] = *(const float4*)(Bg + (size_t)(32 * i) * K);
    }

    float acc[2][8][4];
    #pragma unroll
    for (int mi = 0; mi < 2; mi++)
        #pragma unroll
        for (int ni = 0; ni < 8; ni++)
            #pragma unroll
            for (int q = 0; q < 4; q++) acc[mi][ni][q] = 0.f;

    // ldmatrix per-lane source rows/cols (derived from m8n8.x4 submatrix order)
    const int arow = (lane & 7) + ((lane >> 3) & 1) * 8;  // A: mats {r0-7,k0-3},{r8-15,k0-3},{r0-7,k4-7},{r8-15,k4-7}
    const int acol = (lane >> 4) * 4;
    const int brow = (lane & 7) + ((lane >> 4) & 1) * 8;  // B: mats {n0-7,k0-3},{n0-7,k4-7},{n8-15,k0-3},{n8-15,k4-7}
    const int bcol = ((lane >> 3) & 1) * 4;

    for (int k0 = 0; k0 < K; k0 += 32) {
        __syncthreads();
        #pragma unroll
        for (int i = 0; i < 4; i++) {
            float* dA = &sA[lrow + 32 * i][lcol];
            dA[0] = f2tf(ra[i].x); dA[1] = f2tf(ra[i].y);
            dA[2] = f2tf(ra[i].z); dA[3] = f2tf(ra[i].w);
            float* dB = &sB[lrow + 32 * i][lcol];
            dB[0] = f2tf(rb[i].x); dB[1] = f2tf(rb[i].y);
            dB[2] = f2tf(rb[i].z); dB[3] = f2tf(rb[i].w);
        }
        __syncthreads();
        if (k0 + 32 < K) {
            #pragma unroll
            for (int i = 0; i < 4; i++) {
                ra[i] = *(const float4*)(Ag + (size_t)(32 * i) * K + k0 + 32);
                rb[i] = *(const float4*)(Bg + (size_t)(32 * i) * K + k0 + 32);
            }
        }
        #pragma unroll
        for (int ks = 0; ks < 4; ks++) {
            uint32_t aF[2][4], bF[4][4];
            #pragma unroll
            for (int mi = 0; mi < 2; mi++)
                ldsm4(aF[mi], &sA[wm * 32 + mi * 16 + arow][ks * 8 + acol]);
            #pragma unroll
            for (int nb = 0; nb < 4; nb++)
                ldsm4(bF[nb], &sB[wn * 64 + nb * 16 + brow][ks * 8 + bcol]);
            #pragma unroll
            for (int mi = 0; mi < 2; mi++)
                #pragma unroll
                for (int ni = 0; ni < 8; ni++)
                    mma8(acc[mi][ni], aF[mi], &bF[ni >> 1][(ni & 1) * 2]);
        }
    }

    float f1 = 0.f, f2 = 0.f;
    if (mode == GMODE_RES) { f1 = c1v[layer]; f2 = c2v[layer]; }
    const int gid = lane >> 2, tig = lane & 3;

    #pragma unroll
    for (int mi = 0; mi < 2; mi++) {
        #pragma unroll
        for (int ni = 0; ni < 8; ni++) {
            int col = bn + wn * 64 + ni * 8 + tig * 2;
            #pragma unroll
            for (int h = 0; h < 2; h++) {
                int row = bm + wm * 32 + mi * 16 + gid + h * 8;
                size_t off = (size_t)row * N + col;
                float v0 = acc[mi][ni][h * 2 + 0];
                float v1 = acc[mi][ni][h * 2 + 1];
                if (mode == GMODE_GELU) {
                    v0 = 0.5f * v0 * (1.f + erff(v0 * 0.70710678118654752f));
                    v1 = 0.5f * v1 * (1.f + erff(v1 * 0.70710678118654752f));
                } else if (mode == GMODE_RES) {
                    float2 x0 = *(const float2*)(rx + off);
                    float2 y0 = *(const float2*)(ry + off);
                    v0 = x0.x + f1 * y0.x + f2 * v0;
                    v1 = x0.y + f1 * y0.y + f2 * v1;
                }
                float2 o; o.x = v0; o.y = v1;
                *(float2*)(C + off) = o;
            }
        }
    }
}

// ---------------------------------------------------------------------------
// Fused causal attention + shaped-attention epilogue (fp32 SIMT).
//   y = beta * softmax(QK^T*scale) @ V + alpha * V_row - gamma * pm
// ---------------------------------------------------------------------------
__global__ void __launch_bounds__(256)
attn_kernel(const float* __restrict__ qkbuf, const float* __restrict__ nx,
            const float* __restrict__ pm, float* __restrict__ y,
            const float* __restrict__ al, const float* __restrict__ be,
            const float* __restrict__ ga, int layer)
{
    __shared__ float sQ[64][64];
    __shared__ float sKP[64][64];   // K transposed [d][c]; later P [r][c]
    __shared__ float sV[64][64];
    const int qt = blockIdx.x;
    const int bh = blockIdx.y;
    const int b = bh >> 4;
    const int h = bh & 15;
    const int tid = threadIdx.x;
    const int tx = tid & 15;
    const int ty = tid >> 4;
    const int q0 = qt * 64;
    const float scale = 0.125f;

    for (int i = tid; i < 64 * 16; i += 256) {
        int r = i >> 4, c4 = (i & 15) * 4;
        float4 v = *(const float4*)(qkbuf + (size_t)(b * Tseq + q0 + r) * (2 * Cdim)
                                    + h * 64 + c4);
        sQ[r][c4 + 0] = v.x * scale; sQ[r][c4 + 1] = v.y * scale;
        sQ[r][c4 + 2] = v.z * scale; sQ[r][c4 + 3] = v.w * scale;
    }

    float o[4][4];
    #pragma unroll
    for (int i = 0; i < 4; i++)
        #pragma unroll
        for (int j = 0; j < 4; j++) o[i][j] = 0.f;
    float mrow[4], lrow[4];
    #pragma unroll
    for (int i = 0; i < 4; i++) { mrow[i] = -INFINITY; lrow[i] = 0.f; }

    for (int jt = 0; jt <= qt; jt++) {
        int k0 = jt * 64;
        __syncthreads();
        for (int i = tid; i < 64 * 16; i += 256) {
            int r = i >> 4, c4 = (i & 15) * 4;
            float4 kv = *(const float4*)(qkbuf + (size_t)(b * Tseq + k0 + r) * (2 * Cdim)
                                         + Cdim + h * 64 + c4);
            sKP[c4 + 0][r] = kv.x; sKP[c4 + 1][r] = kv.y;
            sKP[c4 + 2][r] = kv.z; sKP[c4 + 3][r] = kv.w;
            float4 vv = *(const float4*)(nx + (size_t)(b * Tseq + k0 + r) * Cdim
                                         + h * 64 + c4);
            sV[r][c4 + 0] = vv.x; sV[r][c4 + 1] = vv.y;
            sV[r][c4 + 2] = vv.z; sV[r][c4 + 3] = vv.w;
        }
        __syncthreads();

        float s[4][4];
        #pragma unroll
        for (int i = 0; i < 4; i++)
            #pragma unroll
            for (int j = 0; j < 4; j++) s[i][j] = 0.f;
        #pragma unroll 8
        for (int d = 0; d < 64; d++) {
            float qv[4], kv[4];
            #pragma unroll
            for (int i = 0; i < 4; i++) qv[i] = sQ[ty * 4 + i][d];
            #pragma unroll
            for (int j = 0; j < 4; j++) kv[j] = sKP[d][tx + 16 * j];
            #pragma unroll
            for (int i = 0; i < 4; i++)
                #pragma unroll
                for (int j = 0; j < 4; j++)
                    s[i][j] = fmaf(qv[i], kv[j], s[i][j]);
        }
        if (jt == qt) {
            #pragma unroll
            for (int i = 0; i < 4; i++)
                #pragma unroll
                for (int j = 0; j < 4; j++)
                    if (tx + 16 * j > ty * 4 + i) s[i][j] = -INFINITY;
        }

        float corr[4];
        #pragma unroll
        for (int i = 0; i < 4; i++) {
            float mt = fmaxf(fmaxf(s[i][0], s[i][1]), fmaxf(s[i][2], s[i][3]));
            #pragma unroll
            for (int off = 8; off; off >>= 1)
                mt = fmaxf(mt, __shfl_xor_sync(0xffffffffu, mt, off, 16));
            float mnew = fmaxf(mrow[i], mt);
            corr[i] = __expf(mrow[i] - mnew);
            mrow[i] = mnew;
            float sum = 0.f;
            #pragma unroll
            for (int j = 0; j < 4; j++) {
                s[i][j] = __expf(s[i][j] - mnew);
                sum += s[i][j];
            }
            #pragma unroll
            for (int off = 8; off; off >>= 1)
                sum += __shfl_xor_sync(0xffffffffu, sum, off, 16);
            lrow[i] = lrow[i] * corr[i] + sum;
        }

        __syncthreads();
        #pragma unroll
        for (int i = 0; i < 4; i++)
            #pragma unroll
            for (int j = 0; j < 4; j++)
                sKP[ty * 4 + i][tx + 16 * j] = s[i][j];
        __syncthreads();

        #pragma unroll
        for (int i = 0; i < 4; i++)
            #pragma unroll
            for (int j = 0; j < 4; j++) o[i][j] *= corr[i];
        #pragma unroll 8
        for (int k = 0; k < 64; k++) {
            float pv[4], vv[4];
            #pragma unroll
            for (int i = 0; i < 4; i++) pv[i] = sKP[ty * 4 + i][k];
            #pragma unroll
            for (int j = 0; j < 4; j++) vv[j] = sV[k][tx + 16 * j];
            #pragma unroll
            for (int i = 0; i < 4; i++)
                #pragma unroll
                for (int j = 0; j < 4; j++)
                    o[i][j] = fmaf(pv[i], vv[j], o[i][j]);
        }
    }

    float alpha = al[layer], beta = be[layer], gamma = ga[layer];
    #pragma unroll
    for (int i = 0; i < 4; i++) {
        int r = q0 + ty * 4 + i;
        size_t base = (size_t)(b * Tseq + r) * Cdim + h * 64;
        float inv = __fdividef(1.f, lrow[i]);
        #pragma unroll
        for (int j = 0; j < 4; j++) {
            int c = tx + 16 * j;
            y[base + c] = beta * o[i][j] * inv + alpha * nx[base + c]
                          - gamma * pm[base + c];
        }
    }
}

// ---------------------------------------------------------------------------
// Host orchestration
// ---------------------------------------------------------------------------
extern "C" void kernel_launch(void* const* d_in, const int* in_sizes, int n_in,
                              void* d_out, int out_size)
{
    (void)in_sizes; (void)n_in; (void)out_size;
    const int*   ids   = (const int*)  d_in[0];
    const float* wte   = (const float*)d_in[1];
    const float* wpe   = (const float*)d_in[2];
    const float* Wattn = (const float*)d_in[3];
    const float* Wfc   = (const float*)d_in[4];
    const float* Wproj = (const float*)d_in[5];
    const float* ln_w  = (const float*)d_in[6];
    const float* alpha = (const float*)d_in[7];
    const float* beta  = (const float*)d_in[8];
    const float* gamma = (const float*)d_in[9];
    const float* bSA   = (const float*)d_in[10];
    const float* bFF   = (const float*)d_in[11];
    const float* lnf_w = (const float*)d_in[12];
    float* out = (float*)d_out;

    float *x, *nx, *qk, *y, *pm, *ff;
    cudaGetSymbolAddress((void**)&x,  g_x);
    cudaGetSymbolAddress((void**)&nx, g_nx);
    cudaGetSymbolAddress((void**)&qk, g_qk);
    cudaGetSymbolAddress((void**)&y,  g_y);
    cudaGetSymbolAddress((void**)&pm, g_pm);
    cudaGetSymbolAddress((void**)&ff, g_ff);

    embed_kernel<<<BT * Cdim / 4 / 256, 256>>>(ids, wte, wpe);

    for (int i = 0; i < Ln; i++) {
        ln_kernel<<<BT, 256>>>(x, ln_w + (size_t)i * Cdim, nx);
        pm_phase1<<<64, 256>>>(nx);
        pm_phase2<<<64, 256>>>(nx, pm);
        // qk = nx @ Wattn[i]^T : [BT, 2C]
        gemm_nt_tf32<<<dim3(2 * Cdim / 128, BT / 128), 256>>>(
            nx, Wattn + (size_t)i * 2 * Cdim * Cdim, qk,
            BT, 2 * Cdim, Cdim, GMODE_NONE, nullptr, nullptr, nullptr, nullptr, 0);
        // attention branch -> y
        attn_kernel<<<dim3(Tseq / 64, Bsz * Hn), 256>>>(
            qk, nx, pm, y, alpha, beta, gamma, i);
        // h = gelu(nx @ Wfc[i]^T) : [BT, NFF]
        gemm_nt_tf32<<<dim3(NFF / 128, BT / 128), 256>>>(
            nx, Wfc + (size_t)i * NFF * Cdim, ff,
            BT, NFF, Cdim, GMODE_GELU, nullptr, nullptr, nullptr, nullptr, 0);
        // x = x + bSA*y + bFF*(h @ Wproj[i]^T)
        gemm_nt_tf32<<<dim3(Cdim / 128, BT / 128), 256>>>(
            ff, Wproj + (size_t)i * Cdim * NFF, x,
            BT, Cdim, NFF, GMODE_RES, x, y, bSA, bFF, i);
    }

    ln_kernel<<<BT, 256>>>(x, lnf_w, nx);
    // logits = nx @ wte^T : [BT, V]
    gemm_nt_tf32<<<dim3(Vn / 128, BT / 128), 256>>>(
        nx, wte, out, BT, Vn, Cdim, GMODE_NONE,
        nullptr, nullptr, nullptr, nullptr, 0);
}